// round 3
// baseline (speedup 1.0000x reference)
#include <cuda_runtime.h>
#include <cstdint>
#include <cstddef>

#define NN 4096
#define EE 32768
#define HH 1024
#define PP 4096
#define FF 64

// ---------------- device scratch (no dynamic allocation allowed) ----------------
__device__ float g_obj0[NN * HH];
__device__ float g_objA[NN * HH];
__device__ float g_rel0[EE * HH];
__device__ float g_relA[EE * HH];
__device__ float g_relmsg[EE * HH];
__device__ float g_objmsg[NN * HH];
__device__ float g_accS[NN * HH];
__device__ float g_accO[NN * HH];
__device__ float g_cntS[NN];
__device__ float g_cntO[NN];
__device__ float g_rsumR[EE];
__device__ float g_rsqR[EE];
__device__ float g_rsumO[NN];
__device__ float g_rsqO[NN];
__device__ float g_muS[EE];
__device__ float g_rsS[EE];
__device__ float g_muO[EE];
__device__ float g_rsO[EE];
__device__ float g_gate0[EE];
__device__ float g_gate1[EE];
__device__ float g_gate2[EE];
__device__ float g_gate3[EE];

// ---------------- generic 128x128x8 SGEMM, optional dual K-source ----------------
// C[M,Nc] = (reluA? relu:id)(A1) @ B1  [+ (reluA? relu:id)(A2) @ B2]  + bias1 + bias2
// optional relu on output. Shapes must be multiples of tile sizes (they are).
__global__ __launch_bounds__(256) void sgemm_dual(
    const float* __restrict__ A1, const float* __restrict__ B1,
    const float* __restrict__ A2, const float* __restrict__ B2,
    const float* __restrict__ bias1, const float* __restrict__ bias2,
    float* __restrict__ C, int M, int Nc, int K1, int K2, int reluA, int reluC)
{
    __shared__ float As[8][128];
    __shared__ float Bs[8][128];
    const int tid = threadIdx.x;
    const int bx = blockIdx.x, by = blockIdx.y;
    const int tx = tid & 15, ty = tid >> 4;
    const int aRow = tid >> 1, aCol = (tid & 1) << 2;
    const int bRow = tid >> 5, bCol = (tid & 31) << 2;
    float acc[8][8];
#pragma unroll
    for (int i = 0; i < 8; i++)
#pragma unroll
        for (int j = 0; j < 8; j++) acc[i][j] = 0.f;

    const int Kt = K1 + K2;
    for (int k0 = 0; k0 < Kt; k0 += 8) {
        const float* A; const float* B; int kk, K;
        if (k0 < K1) { A = A1; B = B1; kk = k0; K = K1; }
        else         { A = A2; B = B2; kk = k0 - K1; K = K2; }
        float4 av = *(const float4*)(A + (size_t)(by * 128 + aRow) * K + kk + aCol);
        if (reluA) {
            av.x = fmaxf(av.x, 0.f); av.y = fmaxf(av.y, 0.f);
            av.z = fmaxf(av.z, 0.f); av.w = fmaxf(av.w, 0.f);
        }
        As[aCol + 0][aRow] = av.x;
        As[aCol + 1][aRow] = av.y;
        As[aCol + 2][aRow] = av.z;
        As[aCol + 3][aRow] = av.w;
        *(float4*)&Bs[bRow][bCol] =
            *(const float4*)(B + (size_t)(kk + bRow) * Nc + bx * 128 + bCol);
        __syncthreads();
#pragma unroll
        for (int k = 0; k < 8; k++) {
            float a[8], b[8];
            *(float4*)&a[0] = *(float4*)&As[k][ty * 8];
            *(float4*)&a[4] = *(float4*)&As[k][ty * 8 + 4];
            *(float4*)&b[0] = *(float4*)&Bs[k][tx * 8];
            *(float4*)&b[4] = *(float4*)&Bs[k][tx * 8 + 4];
#pragma unroll
            for (int i = 0; i < 8; i++)
#pragma unroll
                for (int j = 0; j < 8; j++) acc[i][j] += a[i] * b[j];
        }
        __syncthreads();
    }

    float bsum[8];
#pragma unroll
    for (int j = 0; j < 8; j++) {
        int col = bx * 128 + tx * 8 + j;
        float v = bias1 ? bias1[col] : 0.f;
        if (bias2) v += bias2[col];
        bsum[j] = v;
    }
#pragma unroll
    for (int i = 0; i < 8; i++) {
        int row = by * 128 + ty * 8 + i;
        float out[8];
#pragma unroll
        for (int j = 0; j < 8; j++) {
            float v = acc[i][j] + bsum[j];
            out[j] = reluC ? fmaxf(v, 0.f) : v;
        }
        *(float4*)(C + (size_t)row * Nc + bx * 128 + tx * 8)     = *(float4*)&out[0];
        *(float4*)(C + (size_t)row * Nc + bx * 128 + tx * 8 + 4) = *(float4*)&out[4];
    }
}

// ---------------- per-row sum / sumsq (for LN stats) ----------------
__global__ void rowstats_kernel(const float* __restrict__ X, float* __restrict__ sum,
                                float* __restrict__ sq, int rows)
{
    int row = blockIdx.x * 8 + (threadIdx.x >> 5);
    int lane = threadIdx.x & 31;
    if (row >= rows) return;
    const float4* p = (const float4*)(X + (size_t)row * HH);
    float s = 0.f, q = 0.f;
#pragma unroll
    for (int i = 0; i < 8; i++) {
        float4 v = p[lane + (i << 5)];
        s += v.x + v.y + v.z + v.w;
        q += v.x * v.x + v.y * v.y + v.z * v.z + v.w * v.w;
    }
#pragma unroll
    for (int o = 16; o > 0; o >>= 1) {
        s += __shfl_down_sync(0xffffffffu, s, o);
        q += __shfl_down_sync(0xffffffffu, q, o);
    }
    if (lane == 0) { sum[row] = s; sq[row] = q; }
}

// ---------------- combine stats per edge: concat({rel_e, obj[idx]}) ----------------
__global__ void edge_stats_kernel(const int* __restrict__ sub, const int* __restrict__ obj,
    const float* __restrict__ sR, const float* __restrict__ qR,
    const float* __restrict__ sO, const float* __restrict__ qO,
    float* __restrict__ muS, float* __restrict__ rsS,
    float* __restrict__ muO, float* __restrict__ rsO)
{
    int e = blockIdx.x * 256 + threadIdx.x;
    if (e >= EE) return;
    float sr = sR[e], qr = qR[e];
    {
        int n = sub[e];
        float s = sr + sO[n], q = qr + qO[n];
        float m = s * (1.f / 2048.f);
        float v = q * (1.f / 2048.f) - m * m;
        muS[e] = m; rsS[e] = rsqrtf(v + 1e-5f);
    }
    {
        int n = obj[e];
        float s = sr + sO[n], q = qr + qO[n];
        float m = s * (1.f / 2048.f);
        float v = q * (1.f / 2048.f) - m * m;
        muO[e] = m; rsO[e] = rsqrtf(v + 1e-5f);
    }
}

// ---------------- fused MPU gate: gate[e] = mean_f sigmoid(relu(LN(x_e)) @ w + b) ----------------
// x_e = concat(first[rowF(e)], second[rowS(e)]), 2048-wide. 32 edges per block.
#define GEB 32
__global__ __launch_bounds__(256) void mpu_gate_kernel(
    const float* __restrict__ first, const int* __restrict__ idxF,
    const float* __restrict__ second, const int* __restrict__ idxS,
    const float* __restrict__ mu, const float* __restrict__ rs,
    const float* __restrict__ lng, const float* __restrict__ lnb,
    const float* __restrict__ w, const float* __restrict__ bf,
    float* __restrict__ gate)
{
    __shared__ float Xs[GEB][68];   // +4 pad: conflict-free reads, float4-aligned stores
    __shared__ float Ws[64][64];
    __shared__ int rF[GEB], rS[GEB];
    __shared__ float mus[GEB], rss[GEB];
    const int tid = threadIdx.x;
    const int e0 = blockIdx.x * GEB;
    if (tid < GEB) {
        int e = e0 + tid;
        rF[tid] = idxF ? idxF[e] : e;
        rS[tid] = idxS ? idxS[e] : e;
        mus[tid] = mu[e];
        rss[tid] = rs[e];
    }
    __syncthreads();
    const int eL = tid >> 3;          // edge within block (0..31)
    const int f0 = (tid & 7) << 3;    // 8 filters per thread
    float acc[8] = {0.f, 0.f, 0.f, 0.f, 0.f, 0.f, 0.f, 0.f};

    for (int c = 0; c < 32; c++) {    // K chunks of 64 over 2048
        const int k0 = c << 6;
        const bool halfFirst = (c < 16);
        // load + normalize X chunk: 32 edges x 64 cols
#pragma unroll
        for (int i = 0; i < 2; i++) {
            int lin = tid + i * 256;
            int e = lin >> 4, q = lin & 15;
            int j = k0 + (q << 2);
            const float* src;
            int col;
            if (halfFirst) { src = first  + (size_t)rF[e] * HH; col = j; }
            else           { src = second + (size_t)rS[e] * HH; col = j - HH; }
            float4 v  = *(const float4*)(src + col);
            float4 gg = *(const float4*)(lng + j);
            float4 bb = *(const float4*)(lnb + j);
            float m_ = mus[e], r_ = rss[e];
            v.x = fmaxf((v.x - m_) * r_ * gg.x + bb.x, 0.f);
            v.y = fmaxf((v.y - m_) * r_ * gg.y + bb.y, 0.f);
            v.z = fmaxf((v.z - m_) * r_ * gg.z + bb.z, 0.f);
            v.w = fmaxf((v.w - m_) * r_ * gg.w + bb.w, 0.f);
            *(float4*)&Xs[e][q << 2] = v;
        }
        // load W chunk: 64 x 64
#pragma unroll
        for (int i = 0; i < 4; i++) {
            int lin = tid + i * 256;
            int kk = lin >> 4, f4 = (lin & 15) << 2;
            *(float4*)&Ws[kk][f4] = *(const float4*)(w + (size_t)(k0 + kk) * FF + f4);
        }
        __syncthreads();
#pragma unroll 8
        for (int kk = 0; kk < 64; kk++) {
            float x = Xs[eL][kk];
            float4 w0 = *(float4*)&Ws[kk][f0];
            float4 w1 = *(float4*)&Ws[kk][f0 + 4];
            acc[0] += x * w0.x; acc[1] += x * w0.y;
            acc[2] += x * w0.z; acc[3] += x * w0.w;
            acc[4] += x * w1.x; acc[5] += x * w1.y;
            acc[6] += x * w1.z; acc[7] += x * w1.w;
        }
        __syncthreads();
    }
    float s = 0.f;
#pragma unroll
    for (int j = 0; j < 8; j++) {
        float v = acc[j] + bf[f0 + j];
        s += 1.f / (1.f + __expf(-v));
    }
    s += __shfl_down_sync(0xffffffffu, s, 4, 8);
    s += __shfl_down_sync(0xffffffffu, s, 2, 8);
    s += __shfl_down_sync(0xffffffffu, s, 1, 8);
    if ((tid & 7) == 0) gate[e0 + eL] = s * (1.f / 64.f);
}

// ---------------- rel_msg = 0.5*(gS*obj[sub] + gO*obj[obj]) ----------------
__global__ void rel_msg_kernel(const float* __restrict__ obj,
                               const int* __restrict__ sub, const int* __restrict__ objx,
                               const float* __restrict__ gS, const float* __restrict__ gO,
                               float* __restrict__ out)
{
    int i = blockIdx.x * 256 + threadIdx.x;   // over E*H/4
    int e = i >> 8;
    int h4 = (i & 255) << 2;
    float4 a = *(const float4*)(obj + (size_t)sub[e]  * HH + h4);
    float4 b = *(const float4*)(obj + (size_t)objx[e] * HH + h4);
    float ga = 0.5f * gS[e], gb = 0.5f * gO[e];
    float4 r;
    r.x = ga * a.x + gb * b.x;
    r.y = ga * a.y + gb * b.y;
    r.z = ga * a.z + gb * b.z;
    r.w = ga * a.w + gb * b.w;
    *(float4*)(out + (size_t)e * HH + h4) = r;
}

// ---------------- scatter: accS[sub[e]] += rel_e*gP2S, accO[obj[e]] += rel_e*gP2O ----------------
__global__ void scatter_kernel(const float* __restrict__ rel,
                               const int* __restrict__ sub, const int* __restrict__ objx,
                               const float* __restrict__ gS, const float* __restrict__ gO,
                               float* __restrict__ accS, float* __restrict__ accO)
{
    int i = blockIdx.x * 256 + threadIdx.x;   // over E*H/4
    int e = i >> 8;
    int h4 = (i & 255) << 2;
    float4 v = *(const float4*)(rel + (size_t)e * HH + h4);
    float gs = gS[e], go = gO[e];
    float* ps = accS + (size_t)sub[e] * HH + h4;
    atomicAdd(ps + 0, v.x * gs);
    atomicAdd(ps + 1, v.y * gs);
    atomicAdd(ps + 2, v.z * gs);
    atomicAdd(ps + 3, v.w * gs);
    float* po = accO + (size_t)objx[e] * HH + h4;
    atomicAdd(po + 0, v.x * go);
    atomicAdd(po + 1, v.y * go);
    atomicAdd(po + 2, v.z * go);
    atomicAdd(po + 3, v.w * go);
}

// ---------------- obj_msg = 0.5*(accS/max(cntS,1) + accO/max(cntO,1)) ----------------
__global__ void objmsg_kernel(const float* __restrict__ accS, const float* __restrict__ accO,
                              const float* __restrict__ cS, const float* __restrict__ cO,
                              float* __restrict__ out)
{
    int i = blockIdx.x * 256 + threadIdx.x;   // over N*H/4
    int n = i >> 8;
    int h4 = (i & 255) << 2;
    float rs_ = 0.5f / fmaxf(cS[n], 1.f);
    float ro_ = 0.5f / fmaxf(cO[n], 1.f);
    float4 a = *(const float4*)(accS + (size_t)n * HH + h4);
    float4 b = *(const float4*)(accO + (size_t)n * HH + h4);
    float4 r;
    r.x = rs_ * a.x + ro_ * b.x;
    r.y = rs_ * a.y + ro_ * b.y;
    r.z = rs_ * a.z + ro_ * b.z;
    r.w = rs_ * a.w + ro_ * b.w;
    *(float4*)(out + (size_t)n * HH + h4) = r;
}

__global__ void zero_kernel(float* __restrict__ p, int n4)
{
    int i = blockIdx.x * 256 + threadIdx.x;
    if (i < n4) *(float4*)(p + (size_t)i * 4) = make_float4(0.f, 0.f, 0.f, 0.f);
}

__global__ void count_kernel(const int* __restrict__ sub, const int* __restrict__ objx,
                             float* __restrict__ cS, float* __restrict__ cO)
{
    int e = blockIdx.x * 256 + threadIdx.x;
    if (e < EE) {
        atomicAdd(&cS[sub[e]], 1.f);
        atomicAdd(&cO[objx[e]], 1.f);
    }
}

// ---------------- host driver ----------------
static float* symaddr(const void* sym)
{
    void* p = nullptr;
    cudaGetSymbolAddress(&p, sym);
    return (float*)p;
}

extern "C" void kernel_launch(void* const* d_in, const int* in_sizes, int n_in,
                              void* d_out, int out_size)
{
    const float* obj_feat   = (const float*)d_in[0];
    const float* rel_feat   = (const float*)d_in[1];
    const int*   sub_idx    = (const int*)d_in[2];
    const int*   obj_idx    = (const int*)d_in[3];
    const float* w_obj_down = (const float*)d_in[4];
    const float* b_obj_down = (const float*)d_in[5];
    const float* w_rel_down = (const float*)d_in[6];
    const float* b_rel_down = (const float*)d_in[7];
    const float* ln_g[4], *ln_b[4], *w_m[4], *b_m[4];
    for (int m = 0; m < 4; m++) {       // 0=s2p, 1=o2p, 2=p2s, 3=p2o
        ln_g[m] = (const float*)d_in[8 + 4 * m];
        ln_b[m] = (const float*)d_in[9 + 4 * m];
        w_m[m]  = (const float*)d_in[10 + 4 * m];
        b_m[m]  = (const float*)d_in[11 + 4 * m];
    }
    const float* wih_objf = (const float*)d_in[24];
    const float* bih_objf = (const float*)d_in[25];
    const float* whh_objf = (const float*)d_in[26];
    const float* bhh_objf = (const float*)d_in[27];
    const float* wih_relf = (const float*)d_in[28];
    const float* bih_relf = (const float*)d_in[29];
    const float* whh_relf = (const float*)d_in[30];
    const float* bhh_relf = (const float*)d_in[31];
    float* out = (float*)d_out;

    float* obj0   = symaddr(g_obj0);
    float* objA   = symaddr(g_objA);
    float* rel0   = symaddr(g_rel0);
    float* relA   = symaddr(g_relA);
    float* relmsg = symaddr(g_relmsg);
    float* objmsg = symaddr(g_objmsg);
    float* accS   = symaddr(g_accS);
    float* accO   = symaddr(g_accO);
    float* cntS   = symaddr(g_cntS);
    float* cntO   = symaddr(g_cntO);
    float* rsumR  = symaddr(g_rsumR);
    float* rsqR   = symaddr(g_rsqR);
    float* rsumO  = symaddr(g_rsumO);
    float* rsqO   = symaddr(g_rsqO);
    float* muS    = symaddr(g_muS);
    float* rsS    = symaddr(g_rsS);
    float* muO    = symaddr(g_muO);
    float* rsO    = symaddr(g_rsO);
    float* gate[4] = { symaddr(g_gate0), symaddr(g_gate1),
                       symaddr(g_gate2), symaddr(g_gate3) };

    // down-dim projections: obj = relu(obj_feat @ Wd + b), rel likewise
    sgemm_dual<<<dim3(HH / 128, NN / 128), 256>>>(
        obj_feat, w_obj_down, nullptr, nullptr, b_obj_down, nullptr,
        obj0, NN, HH, PP, 0, 0, 1);
    sgemm_dual<<<dim3(HH / 128, EE / 128), 256>>>(
        rel_feat, w_rel_down, nullptr, nullptr, b_rel_down, nullptr,
        rel0, EE, HH, PP, 0, 0, 1);

    // edge counts per node (constant across iterations)
    zero_kernel<<<(NN / 4 + 255) / 256, 256>>>(cntS, NN / 4);
    zero_kernel<<<(NN / 4 + 255) / 256, 256>>>(cntO, NN / 4);
    count_kernel<<<EE / 256, 256>>>(sub_idx, obj_idx, cntS, cntO);

    float* objCur = obj0;
    float* relCur = rel0;
    for (int it = 0; it < 2; it++) {
        float* objNext = (it == 0) ? objA : out;
        float* relNext = (it == 0) ? relA : out + (size_t)NN * HH;

        // LN stats
        rowstats_kernel<<<EE / 8, 256>>>(relCur, rsumR, rsqR, EE);
        rowstats_kernel<<<NN / 8, 256>>>(objCur, rsumO, rsqO, NN);
        edge_stats_kernel<<<EE / 256, 256>>>(sub_idx, obj_idx, rsumR, rsqR,
                                             rsumO, rsqO, muS, rsS, muO, rsO);
        // gates: s2p=[rel,sub_h], o2p=[rel,obj_h], p2s=[sub_h,rel], p2o=[obj_h,rel]
        mpu_gate_kernel<<<EE / GEB, 256>>>(relCur, nullptr, objCur, sub_idx,
                                           muS, rsS, ln_g[0], ln_b[0], w_m[0], b_m[0], gate[0]);
        mpu_gate_kernel<<<EE / GEB, 256>>>(relCur, nullptr, objCur, obj_idx,
                                           muO, rsO, ln_g[1], ln_b[1], w_m[1], b_m[1], gate[1]);
        mpu_gate_kernel<<<EE / GEB, 256>>>(objCur, sub_idx, relCur, nullptr,
                                           muS, rsS, ln_g[2], ln_b[2], w_m[2], b_m[2], gate[2]);
        mpu_gate_kernel<<<EE / GEB, 256>>>(objCur, obj_idx, relCur, nullptr,
                                           muO, rsO, ln_g[3], ln_b[3], w_m[3], b_m[3], gate[3]);

        // messages
        rel_msg_kernel<<<EE * (HH / 4) / 256, 256>>>(objCur, sub_idx, obj_idx,
                                                     gate[0], gate[1], relmsg);
        zero_kernel<<<(NN * HH / 4 + 255) / 256, 256>>>(accS, NN * HH / 4);
        zero_kernel<<<(NN * HH / 4 + 255) / 256, 256>>>(accO, NN * HH / 4);
        scatter_kernel<<<EE * (HH / 4) / 256, 256>>>(relCur, sub_idx, obj_idx,
                                                     gate[2], gate[3], accS, accO);
        objmsg_kernel<<<NN * (HH / 4) / 256, 256>>>(accS, accO, cntS, cntO, objmsg);

        // fusion: C = relu(msg)@Wih + relu(cur)@Whh + bih + bhh
        sgemm_dual<<<dim3(HH / 128, NN / 128), 256>>>(
            objmsg, wih_objf, objCur, whh_objf, bih_objf, bhh_objf,
            objNext, NN, HH, HH, HH, 1, 0);
        sgemm_dual<<<dim3(HH / 128, EE / 128), 256>>>(
            relmsg, wih_relf, relCur, whh_relf, bih_relf, bhh_relf,
            relNext, EE, HH, HH, HH, 1, 0);

        objCur = objNext;
        relCur = relNext;
    }
}

// round 10
// speedup vs baseline: 2.7828x; 2.7828x over previous
#include <cuda_runtime.h>
#include <cuda_bf16.h>
#include <cstdint>
#include <cstddef>

#define NN 4096
#define EE 32768
#define HH 1024
#define PP 4096
#define FF 64

// ======================= portable PTX helpers (no sm_103a-only ops) =======================
__device__ __forceinline__ uint32_t smem_u32(const void* p) {
    uint32_t a;
    asm("{ .reg .u64 t; cvta.to.shared.u64 t, %1; cvt.u32.u64 %0, t; }" : "=r"(a) : "l"(p));
    return a;
}
__device__ __forceinline__ void ldsm_x4(uint32_t* r, uint32_t addr) {
    asm volatile("ldmatrix.sync.aligned.m8n8.x4.shared.b16 {%0,%1,%2,%3}, [%4];"
        : "=r"(r[0]), "=r"(r[1]), "=r"(r[2]), "=r"(r[3]) : "r"(addr));
}
// NON-trans: B stored [N][K] k-contiguous already matches the row.col mma B fragment.
__device__ __forceinline__ void ldsm_x2(uint32_t* r, uint32_t addr) {
    asm volatile("ldmatrix.sync.aligned.m8n8.x2.shared.b16 {%0,%1}, [%2];"
        : "=r"(r[0]), "=r"(r[1]) : "r"(addr));
}
__device__ __forceinline__ void mma_bf16(float* c, const uint32_t* a, const uint32_t* b) {
    asm volatile("mma.sync.aligned.m16n8k16.row.col.f32.bf16.bf16.f32 "
        "{%0,%1,%2,%3}, {%4,%5,%6,%7}, {%8,%9}, {%0,%1,%2,%3};"
        : "+f"(c[0]), "+f"(c[1]), "+f"(c[2]), "+f"(c[3])
        : "r"(a[0]), "r"(a[1]), "r"(a[2]), "r"(a[3]), "r"(b[0]), "r"(b[1]));
}
__device__ __forceinline__ uint32_t pack_bf16(float v0, float v1) {
    __nv_bfloat162 h = __floats2bfloat162_rn(v0, v1);
    return *reinterpret_cast<uint32_t*>(&h);
}

// ======================= device scratch =======================
__device__ float g_obj0[NN * HH];
__device__ float g_objA[NN * HH];
__device__ float g_rel0[EE * HH];
__device__ float g_relA[EE * HH];
__device__ float g_relmsg[EE * HH];
__device__ float g_objmsg[NN * HH];
__device__ float g_accS[NN * HH];
__device__ float g_accO[NN * HH];
__device__ float g_cntS[NN];
__device__ float g_cntO[NN];
__device__ float g_rsumR[EE];
__device__ float g_rsqR[EE];
__device__ float g_rsumO[NN];
__device__ float g_rsqO[NN];
__device__ float g_muS[EE];
__device__ float g_rsS[EE];
__device__ float g_muO[EE];
__device__ float g_rsO[EE];
__device__ float g_gate0[EE];
__device__ float g_gate1[EE];
__device__ float g_gate2[EE];
__device__ float g_gate3[EE];
__device__ float g_gateout[EE * FF];
// pre-transposed + bf16-split weights ([N][K] row-major)
__device__ __nv_bfloat16 g_wdobj_hi[HH * PP];
__device__ __nv_bfloat16 g_wdobj_lo[HH * PP];
__device__ __nv_bfloat16 g_wdrel_hi[HH * PP];
__device__ __nv_bfloat16 g_wdrel_lo[HH * PP];
__device__ __nv_bfloat16 g_wg_hi[4 * FF * 2 * HH];
__device__ __nv_bfloat16 g_wg_lo[4 * FF * 2 * HH];
__device__ __nv_bfloat16 g_wf_hi[4 * HH * HH];  // wih_objf, whh_objf, wih_relf, whh_relf
__device__ __nv_bfloat16 g_wf_lo[4 * HH * HH];

// ======================= weight prep: W[K,N] -> hi/lo bf16 [N][K] =======================
__global__ void transpose_split(const float* __restrict__ W, int K, int N,
                                __nv_bfloat16* __restrict__ hi, __nv_bfloat16* __restrict__ lo)
{
    __shared__ float tile[32][33];
    int n0 = blockIdx.x * 32, k0 = blockIdx.y * 32;
    int tx = threadIdx.x, ty = threadIdx.y;   // (32, 8)
#pragma unroll
    for (int i = 0; i < 32; i += 8)
        tile[ty + i][tx] = W[(size_t)(k0 + ty + i) * N + n0 + tx];
    __syncthreads();
#pragma unroll
    for (int i = 0; i < 32; i += 8) {
        float v = tile[tx][ty + i];
        __nv_bfloat16 h = __float2bfloat16_rn(v);
        size_t o = (size_t)(n0 + ty + i) * K + k0 + tx;
        hi[o] = h;
        lo[o] = __float2bfloat16_rn(v - __bfloat162float(h));
    }
}

// ======================= bf16x3 mma.sync GEMM =======================
// C[M,N] = f(A) @ B^T + bias1 (+bias2), f = id / relu / relu(LN(.)), virtual K = K1(+K2).
// A fp32 (optionally row-gathered); B pre-split bf16 hi/lo, [N][ldB] row-major.
template<int BN, bool DUAL, bool RELU_A, bool LN>
__global__ __launch_bounds__(256, 1)
void gemm_mma(const float* __restrict__ A1, const int* __restrict__ idx1, int ldA1, int K1,
              const float* __restrict__ A2, const int* __restrict__ idx2, int ldA2, int K2,
              const __nv_bfloat16* __restrict__ Bhi1, const __nv_bfloat16* __restrict__ Blo1, int ldB1,
              const __nv_bfloat16* __restrict__ Bhi2, const __nv_bfloat16* __restrict__ Blo2, int ldB2,
              const float* __restrict__ mu, const float* __restrict__ rsg,
              const float* __restrict__ lng, const float* __restrict__ lnb,
              const float* __restrict__ bias1, const float* __restrict__ bias2,
              float* __restrict__ C, int ldC, int reluC)
{
    constexpr int WARPS_M = (BN == 128) ? 2 : 4;
    constexpr int WM = 128 / WARPS_M;          // 64 or 32
    constexpr int MT = WM / 16;                // 4 or 2
    constexpr int NT = 4;                      // WN = 32
    constexpr int AST = 40;                    // smem row stride in halves (80B, 16B-aligned)
    constexpr int A_HALVES = 128 * AST;
    constexpr int B_HALVES = BN * AST;
    constexpr int STAGE = 2 * A_HALVES + 2 * B_HALVES;  // hi+lo for A and B
    constexpr int NB = (BN * 4) / 256;         // B uint4 chunks per thread (2 or 1)

    extern __shared__ __nv_bfloat16 sm[];
    const int t = threadIdx.x;
    const int wid = t >> 5, lane = t & 31;
    const int wm = wid % WARPS_M, wn = wid / WARPS_M;

    const int blockM = blockIdx.y * 128;
    const int n0 = blockIdx.x * BN;

    // ---- producer setup: 2 threads per A row, 16 floats each ----
    const int arow = t >> 1, ahalf = t & 1;
    const int row_m = blockM + arow;
    int r1 = row_m, r2 = row_m;
    if (LN) { if (idx1) r1 = idx1[row_m]; if (idx2) r2 = idx2[row_m]; }
    float mu_t = 0.f, rs_t = 0.f;
    if (LN) { mu_t = mu[row_m]; rs_t = rsg[row_m]; }
    const float* rowA1 = A1 + (size_t)r1 * ldA1;
    const float* rowA2 = DUAL ? (A2 + (size_t)r2 * ldA2) : A1;

    const int nChunks = (K1 + (DUAL ? K2 : 0)) / 32;

    // ---- per-lane ldmatrix offsets ----
    const int a_row_off = (lane & 7) | (((lane >> 3) & 1) << 3);
    const int a_kh = (lane >> 4) << 3;
    const int b_row_off = lane & 7;
    const int b_kh = ((lane >> 3) & 1) << 3;

    float acc[MT][NT][4];
#pragma unroll
    for (int i = 0; i < MT; i++)
#pragma unroll
        for (int j = 0; j < NT; j++)
#pragma unroll
            for (int k = 0; k < 4; k++) acc[i][j][k] = 0.f;

    // staging registers
    float fA[16];
    uint4 bHiS[NB], bLoS[NB];

    auto loadA = [&](int c) {
        int k0v = c * 32;
        bool fh = (!DUAL) || (k0v < K1);
        const float* src = (fh ? rowA1 + k0v : rowA2 + (k0v - K1)) + ahalf * 16;
        int jb = k0v + ahalf * 16;
#pragma unroll
        for (int q = 0; q < 4; q++) {
            float4 v = ((const float4*)src)[q];
            if (LN) {
                int j = jb + q * 4;
                float4 g = *(const float4*)(lng + j);
                float4 bb = *(const float4*)(lnb + j);
                v.x = fmaxf(fmaf((v.x - mu_t) * rs_t, g.x, bb.x), 0.f);
                v.y = fmaxf(fmaf((v.y - mu_t) * rs_t, g.y, bb.y), 0.f);
                v.z = fmaxf(fmaf((v.z - mu_t) * rs_t, g.z, bb.z), 0.f);
                v.w = fmaxf(fmaf((v.w - mu_t) * rs_t, g.w, bb.w), 0.f);
            } else if (RELU_A) {
                v.x = fmaxf(v.x, 0.f); v.y = fmaxf(v.y, 0.f);
                v.z = fmaxf(v.z, 0.f); v.w = fmaxf(v.w, 0.f);
            }
            fA[q * 4 + 0] = v.x; fA[q * 4 + 1] = v.y;
            fA[q * 4 + 2] = v.z; fA[q * 4 + 3] = v.w;
        }
    };
    auto loadB = [&](int c) {
        int k0v = c * 32;
        bool fh = (!DUAL) || (k0v < K1);
        const __nv_bfloat16* bh = fh ? Bhi1 : Bhi2;
        const __nv_bfloat16* bl = fh ? Blo1 : Blo2;
        int ldB = fh ? ldB1 : ldB2;
        int kk = fh ? k0v : (k0v - K1);
#pragma unroll
        for (int i = 0; i < NB; i++) {
            int idx = t + i * 256;
            int row = idx >> 2, q = idx & 3;
            const __nv_bfloat16* p = bh + (size_t)(n0 + row) * ldB + kk;
            const __nv_bfloat16* pl = bl + (size_t)(n0 + row) * ldB + kk;
            bHiS[i] = ((const uint4*)p)[q];
            bLoS[i] = ((const uint4*)pl)[q];
        }
    };
    auto storeA = [&](int buf) {
        __nv_bfloat16* sA = sm + buf * STAGE;
        __nv_bfloat16* sAlo = sA + A_HALVES;
        uint32_t h[8], l[8];
#pragma unroll
        for (int i = 0; i < 8; i++) {
            float v0 = fA[2 * i], v1 = fA[2 * i + 1];
            __nv_bfloat16 h0 = __float2bfloat16_rn(v0), h1 = __float2bfloat16_rn(v1);
            __nv_bfloat162 hp; hp.x = h0; hp.y = h1;
            h[i] = *reinterpret_cast<uint32_t*>(&hp);
            l[i] = pack_bf16(v0 - __bfloat162float(h0), v1 - __bfloat162float(h1));
        }
        int base = arow * AST + ahalf * 16;
        *(uint4*)(sA + base)       = make_uint4(h[0], h[1], h[2], h[3]);
        *(uint4*)(sA + base + 8)   = make_uint4(h[4], h[5], h[6], h[7]);
        *(uint4*)(sAlo + base)     = make_uint4(l[0], l[1], l[2], l[3]);
        *(uint4*)(sAlo + base + 8) = make_uint4(l[4], l[5], l[6], l[7]);
    };
    auto storeB = [&](int buf) {
        __nv_bfloat16* sB = sm + buf * STAGE + 2 * A_HALVES;
        __nv_bfloat16* sBlo = sB + B_HALVES;
#pragma unroll
        for (int i = 0; i < NB; i++) {
            int idx = t + i * 256;
            int row = idx >> 2, q = idx & 3;
            ((uint4*)(sB + row * AST))[q] = bHiS[i];
            ((uint4*)(sBlo + row * AST))[q] = bLoS[i];
        }
    };
    auto domma = [&](int buf) {
        uint32_t aHi = smem_u32(sm + buf * STAGE);
        uint32_t aLo = aHi + A_HALVES * 2;
        uint32_t bHi = aHi + 2 * A_HALVES * 2;
        uint32_t bLo = bHi + B_HALVES * 2;
#pragma unroll
        for (int ks = 0; ks < 2; ks++) {
            uint32_t ah[MT][4], al[MT][4], bh[NT][2], bl[NT][2];
#pragma unroll
            for (int mt = 0; mt < MT; mt++) {
                uint32_t off = (uint32_t)((wm * WM + mt * 16 + a_row_off) * AST + ks * 16 + a_kh) * 2;
                ldsm_x4(ah[mt], aHi + off);
                ldsm_x4(al[mt], aLo + off);
            }
#pragma unroll
            for (int nt = 0; nt < NT; nt++) {
                uint32_t off = (uint32_t)((wn * 32 + nt * 8 + b_row_off) * AST + ks * 16 + b_kh) * 2;
                ldsm_x2(bh[nt], bHi + off);
                ldsm_x2(bl[nt], bLo + off);
            }
#pragma unroll
            for (int mt = 0; mt < MT; mt++)
#pragma unroll
                for (int nt = 0; nt < NT; nt++) mma_bf16(acc[mt][nt], ah[mt], bh[nt]);
#pragma unroll
            for (int mt = 0; mt < MT; mt++)
#pragma unroll
                for (int nt = 0; nt < NT; nt++) mma_bf16(acc[mt][nt], ah[mt], bl[nt]);
#pragma unroll
            for (int mt = 0; mt < MT; mt++)
#pragma unroll
                for (int nt = 0; nt < NT; nt++) mma_bf16(acc[mt][nt], al[mt], bh[nt]);
        }
    };

    // ---- pipeline ----
    loadA(0); loadB(0);
    storeA(0); storeB(0);
    __syncthreads();
    for (int c = 0; c < nChunks; c++) {
        if (c + 1 < nChunks) { loadA(c + 1); loadB(c + 1); }
        domma(c & 1);
        if (c + 1 < nChunks) { storeA((c + 1) & 1); storeB((c + 1) & 1); }
        __syncthreads();
    }

    // ---- epilogue ----
#pragma unroll
    for (int nt = 0; nt < NT; nt++) {
        int col = n0 + wn * 32 + nt * 8 + (lane & 3) * 2;
        float b0 = bias1 ? bias1[col] : 0.f;
        float b1 = bias1 ? bias1[col + 1] : 0.f;
        if (bias2) { b0 += bias2[col]; b1 += bias2[col + 1]; }
#pragma unroll
        for (int mt = 0; mt < MT; mt++) {
            int r0 = blockM + wm * WM + mt * 16 + (lane >> 2);
            float2 o0, o1;
            o0.x = acc[mt][nt][0] + b0; o0.y = acc[mt][nt][1] + b1;
            o1.x = acc[mt][nt][2] + b0; o1.y = acc[mt][nt][3] + b1;
            if (reluC) {
                o0.x = fmaxf(o0.x, 0.f); o0.y = fmaxf(o0.y, 0.f);
                o1.x = fmaxf(o1.x, 0.f); o1.y = fmaxf(o1.y, 0.f);
            }
            *(float2*)(C + (size_t)r0 * ldC + col) = o0;
            *(float2*)(C + (size_t)(r0 + 8) * ldC + col) = o1;
        }
    }
}

// ======================= gate reduce: gate[e] = mean_f sigmoid(X[e,f]) =======================
__global__ void gate_reduce(const float* __restrict__ X, float* __restrict__ gate)
{
    int row = blockIdx.x * 8 + (threadIdx.x >> 5);
    int lane = threadIdx.x & 31;
    float2 v = ((const float2*)(X + (size_t)row * FF))[lane];
    float s = 1.f / (1.f + __expf(-v.x)) + 1.f / (1.f + __expf(-v.y));
#pragma unroll
    for (int o = 16; o > 0; o >>= 1) s += __shfl_down_sync(0xffffffffu, s, o);
    if (lane == 0) gate[row] = s * (1.f / (float)FF);
}

// ======================= elementwise kernels (validated in R2) =======================
__global__ void rowstats_kernel(const float* __restrict__ X, float* __restrict__ sum,
                                float* __restrict__ sq, int rows)
{
    int row = blockIdx.x * 8 + (threadIdx.x >> 5);
    int lane = threadIdx.x & 31;
    if (row >= rows) return;
    const float4* p = (const float4*)(X + (size_t)row * HH);
    float s = 0.f, q = 0.f;
#pragma unroll
    for (int i = 0; i < 8; i++) {
        float4 v = p[lane + (i << 5)];
        s += v.x + v.y + v.z + v.w;
        q += v.x * v.x + v.y * v.y + v.z * v.z + v.w * v.w;
    }
#pragma unroll
    for (int o = 16; o > 0; o >>= 1) {
        s += __shfl_down_sync(0xffffffffu, s, o);
        q += __shfl_down_sync(0xffffffffu, q, o);
    }
    if (lane == 0) { sum[row] = s; sq[row] = q; }
}

__global__ void edge_stats_kernel(const int* __restrict__ sub, const int* __restrict__ obj,
    const float* __restrict__ sR, const float* __restrict__ qR,
    const float* __restrict__ sO, const float* __restrict__ qO,
    float* __restrict__ muS, float* __restrict__ rsS,
    float* __restrict__ muO, float* __restrict__ rsO)
{
    int e = blockIdx.x * 256 + threadIdx.x;
    if (e >= EE) return;
    float sr = sR[e], qr = qR[e];
    {
        int n = sub[e];
        float s = sr + sO[n], q = qr + qO[n];
        float m = s * (1.f / 2048.f);
        float v = q * (1.f / 2048.f) - m * m;
        muS[e] = m; rsS[e] = rsqrtf(v + 1e-5f);
    }
    {
        int n = obj[e];
        float s = sr + sO[n], q = qr + qO[n];
        float m = s * (1.f / 2048.f);
        float v = q * (1.f / 2048.f) - m * m;
        muO[e] = m; rsO[e] = rsqrtf(v + 1e-5f);
    }
}

__global__ void rel_msg_kernel(const float* __restrict__ obj,
                               const int* __restrict__ sub, const int* __restrict__ objx,
                               const float* __restrict__ gS, const float* __restrict__ gO,
                               float* __restrict__ out)
{
    int i = blockIdx.x * 256 + threadIdx.x;
    int e = i >> 8;
    int h4 = (i & 255) << 2;
    float4 a = *(const float4*)(obj + (size_t)sub[e]  * HH + h4);
    float4 b = *(const float4*)(obj + (size_t)objx[e] * HH + h4);
    float ga = 0.5f * gS[e], gb = 0.5f * gO[e];
    float4 r;
    r.x = ga * a.x + gb * b.x;
    r.y = ga * a.y + gb * b.y;
    r.z = ga * a.z + gb * b.z;
    r.w = ga * a.w + gb * b.w;
    *(float4*)(out + (size_t)e * HH + h4) = r;
}

__global__ void scatter_kernel(const float* __restrict__ rel,
                               const int* __restrict__ sub, const int* __restrict__ objx,
                               const float* __restrict__ gS, const float* __restrict__ gO,
                               float* __restrict__ accS, float* __restrict__ accO)
{
    int i = blockIdx.x * 256 + threadIdx.x;
    int e = i >> 8;
    int h4 = (i & 255) << 2;
    float4 v = *(const float4*)(rel + (size_t)e * HH + h4);
    float gs = gS[e], go = gO[e];
    float* ps = accS + (size_t)sub[e] * HH + h4;
    atomicAdd(ps + 0, v.x * gs);
    atomicAdd(ps + 1, v.y * gs);
    atomicAdd(ps + 2, v.z * gs);
    atomicAdd(ps + 3, v.w * gs);
    float* po = accO + (size_t)objx[e] * HH + h4;
    atomicAdd(po + 0, v.x * go);
    atomicAdd(po + 1, v.y * go);
    atomicAdd(po + 2, v.z * go);
    atomicAdd(po + 3, v.w * go);
}

__global__ void objmsg_kernel(const float* __restrict__ accS, const float* __restrict__ accO,
                              const float* __restrict__ cS, const float* __restrict__ cO,
                              float* __restrict__ out)
{
    int i = blockIdx.x * 256 + threadIdx.x;
    int n = i >> 8;
    int h4 = (i & 255) << 2;
    float rs_ = 0.5f / fmaxf(cS[n], 1.f);
    float ro_ = 0.5f / fmaxf(cO[n], 1.f);
    float4 a = *(const float4*)(accS + (size_t)n * HH + h4);
    float4 b = *(const float4*)(accO + (size_t)n * HH + h4);
    float4 r;
    r.x = rs_ * a.x + ro_ * b.x;
    r.y = rs_ * a.y + ro_ * b.y;
    r.z = rs_ * a.z + ro_ * b.z;
    r.w = rs_ * a.w + ro_ * b.w;
    *(float4*)(out + (size_t)n * HH + h4) = r;
}

__global__ void zero_kernel(float* __restrict__ p, int n4)
{
    int i = blockIdx.x * 256 + threadIdx.x;
    if (i < n4) *(float4*)(p + (size_t)i * 4) = make_float4(0.f, 0.f, 0.f, 0.f);
}

__global__ void count_kernel(const int* __restrict__ sub, const int* __restrict__ objx,
                             float* __restrict__ cS, float* __restrict__ cO)
{
    int e = blockIdx.x * 256 + threadIdx.x;
    if (e < EE) {
        atomicAdd(&cS[sub[e]], 1.f);
        atomicAdd(&cO[objx[e]], 1.f);
    }
}

// ======================= host driver =======================
template<typename T>
static T* symaddrT(const void* sym)
{
    void* p = nullptr;
    cudaGetSymbolAddress(&p, sym);
    return (T*)p;
}

extern "C" void kernel_launch(void* const* d_in, const int* in_sizes, int n_in,
                              void* d_out, int out_size)
{
    const float* obj_feat   = (const float*)d_in[0];
    const float* rel_feat   = (const float*)d_in[1];
    const int*   sub_idx    = (const int*)d_in[2];
    const int*   obj_idx    = (const int*)d_in[3];
    const float* w_obj_down = (const float*)d_in[4];
    const float* b_obj_down = (const float*)d_in[5];
    const float* w_rel_down = (const float*)d_in[6];
    const float* b_rel_down = (const float*)d_in[7];
    const float *ln_g[4], *ln_b[4], *w_m[4], *b_m[4];
    for (int m = 0; m < 4; m++) {       // 0=s2p, 1=o2p, 2=p2s, 3=p2o
        ln_g[m] = (const float*)d_in[8 + 4 * m];
        ln_b[m] = (const float*)d_in[9 + 4 * m];
        w_m[m]  = (const float*)d_in[10 + 4 * m];
        b_m[m]  = (const float*)d_in[11 + 4 * m];
    }
    const float* wf[4]  = { (const float*)d_in[24], (const float*)d_in[26],
                            (const float*)d_in[28], (const float*)d_in[30] };
    const float* bih_objf = (const float*)d_in[25];
    const float* bhh_objf = (const float*)d_in[27];
    const float* bih_relf = (const float*)d_in[29];
    const float* bhh_relf = (const float*)d_in[31];
    float* out = (float*)d_out;

    float* obj0    = symaddrT<float>(g_obj0);
    float* objA    = symaddrT<float>(g_objA);
    float* rel0    = symaddrT<float>(g_rel0);
    float* relA    = symaddrT<float>(g_relA);
    float* relmsg  = symaddrT<float>(g_relmsg);
    float* objmsg  = symaddrT<float>(g_objmsg);
    float* accS    = symaddrT<float>(g_accS);
    float* accO    = symaddrT<float>(g_accO);
    float* cntS    = symaddrT<float>(g_cntS);
    float* cntO    = symaddrT<float>(g_cntO);
    float* rsumR   = symaddrT<float>(g_rsumR);
    float* rsqR    = symaddrT<float>(g_rsqR);
    float* rsumO   = symaddrT<float>(g_rsumO);
    float* rsqO    = symaddrT<float>(g_rsqO);
    float* muS     = symaddrT<float>(g_muS);
    float* rsS     = symaddrT<float>(g_rsS);
    float* muO     = symaddrT<float>(g_muO);
    float* rsO     = symaddrT<float>(g_rsO);
    float* gateout = symaddrT<float>(g_gateout);
    float* gate[4] = { symaddrT<float>(g_gate0), symaddrT<float>(g_gate1),
                       symaddrT<float>(g_gate2), symaddrT<float>(g_gate3) };
    __nv_bfloat16* wdobj_hi = symaddrT<__nv_bfloat16>(g_wdobj_hi);
    __nv_bfloat16* wdobj_lo = symaddrT<__nv_bfloat16>(g_wdobj_lo);
    __nv_bfloat16* wdrel_hi = symaddrT<__nv_bfloat16>(g_wdrel_hi);
    __nv_bfloat16* wdrel_lo = symaddrT<__nv_bfloat16>(g_wdrel_lo);
    __nv_bfloat16* wg_hi    = symaddrT<__nv_bfloat16>(g_wg_hi);
    __nv_bfloat16* wg_lo    = symaddrT<__nv_bfloat16>(g_wg_lo);
    __nv_bfloat16* wf_hi    = symaddrT<__nv_bfloat16>(g_wf_hi);
    __nv_bfloat16* wf_lo    = symaddrT<__nv_bfloat16>(g_wf_lo);

    // ---- weight prep ----
    {
        dim3 blk(32, 8);
        transpose_split<<<dim3(HH / 32, PP / 32), blk>>>(w_obj_down, PP, HH, wdobj_hi, wdobj_lo);
        transpose_split<<<dim3(HH / 32, PP / 32), blk>>>(w_rel_down, PP, HH, wdrel_hi, wdrel_lo);
        for (int m = 0; m < 4; m++)
            transpose_split<<<dim3(FF / 32, 2 * HH / 32), blk>>>(
                w_m[m], 2 * HH, FF,
                wg_hi + (size_t)m * FF * 2 * HH, wg_lo + (size_t)m * FF * 2 * HH);
        for (int m = 0; m < 4; m++)
            transpose_split<<<dim3(HH / 32, HH / 32), blk>>>(
                wf[m], HH, HH,
                wf_hi + (size_t)m * HH * HH, wf_lo + (size_t)m * HH * HH);
    }

    // dynamic smem: double-buffered (A hi/lo + B hi/lo), 80B rows
    constexpr int SM128 = 2 * (2 * 128 * 40 + 2 * 128 * 40) * 2;   // 81920 B
    constexpr int SM64  = 2 * (2 * 128 * 40 + 2 * 64 * 40) * 2;    // 61440 B
    auto kPlain = gemm_mma<128, false, false, false>;
    auto kFuse  = gemm_mma<128, true,  true,  false>;
    auto kGate  = gemm_mma<64,  true,  false, true>;
    cudaFuncSetAttribute(kPlain, cudaFuncAttributeMaxDynamicSharedMemorySize, SM128);
    cudaFuncSetAttribute(kFuse,  cudaFuncAttributeMaxDynamicSharedMemorySize, SM128);
    cudaFuncSetAttribute(kGate,  cudaFuncAttributeMaxDynamicSharedMemorySize, SM64);

    // ---- down-dim projections: relu(X @ Wd + b) ----
    kPlain<<<dim3(HH / 128, NN / 128), 256, SM128>>>(
        obj_feat, nullptr, PP, PP, nullptr, nullptr, 0, 0,
        wdobj_hi, wdobj_lo, PP, nullptr, nullptr, 0,
        nullptr, nullptr, nullptr, nullptr,
        b_obj_down, nullptr, obj0, HH, 1);
    kPlain<<<dim3(HH / 128, EE / 128), 256, SM128>>>(
        rel_feat, nullptr, PP, PP, nullptr, nullptr, 0, 0,
        wdrel_hi, wdrel_lo, PP, nullptr, nullptr, 0,
        nullptr, nullptr, nullptr, nullptr,
        b_rel_down, nullptr, rel0, HH, 1);

    // ---- per-node edge counts ----
    zero_kernel<<<(NN / 4 + 255) / 256, 256>>>(cntS, NN / 4);
    zero_kernel<<<(NN / 4 + 255) / 256, 256>>>(cntO, NN / 4);
    count_kernel<<<EE / 256, 256>>>(sub_idx, obj_idx, cntS, cntO);

    float* objCur = obj0;
    float* relCur = rel0;
    for (int it = 0; it < 2; it++) {
        float* objNext = (it == 0) ? objA : out;
        float* relNext = (it == 0) ? relA : out + (size_t)NN * HH;

        // LN stats (shared across the 4 MPUs)
        rowstats_kernel<<<EE / 8, 256>>>(relCur, rsumR, rsqR, EE);
        rowstats_kernel<<<NN / 8, 256>>>(objCur, rsumO, rsqO, NN);
        edge_stats_kernel<<<EE / 256, 256>>>(sub_idx, obj_idx, rsumR, rsqR,
                                             rsumO, rsqO, muS, rsS, muO, rsO);

        // gates: concat order (first, second); LN+relu fused into A producer
        const float* fsrc[4]  = { relCur, relCur, objCur, objCur };
        const int*   fidx[4]  = { nullptr, nullptr, sub_idx, obj_idx };
        const float* ssrc[4]  = { objCur, objCur, relCur, relCur };
        const int*   sidx[4]  = { sub_idx, obj_idx, nullptr, nullptr };
        const float* gmu[4]   = { muS, muO, muS, muO };
        const float* grs[4]   = { rsS, rsO, rsS, rsO };
        for (int m = 0; m < 4; m++) {
            kGate<<<dim3(1, EE / 128), 256, SM64>>>(
                fsrc[m], fidx[m], HH, HH, ssrc[m], sidx[m], HH, HH,
                wg_hi + (size_t)m * FF * 2 * HH, wg_lo + (size_t)m * FF * 2 * HH, 2 * HH,
                wg_hi + (size_t)m * FF * 2 * HH + HH, wg_lo + (size_t)m * FF * 2 * HH + HH, 2 * HH,
                gmu[m], grs[m], ln_g[m], ln_b[m],
                b_m[m], nullptr, gateout, FF, 0);
            gate_reduce<<<EE / 8, 256>>>(gateout, gate[m]);
        }

        // messages
        rel_msg_kernel<<<EE * (HH / 4) / 256, 256>>>(objCur, sub_idx, obj_idx,
                                                     gate[0], gate[1], relmsg);
        zero_kernel<<<(NN * HH / 4 + 255) / 256, 256>>>(accS, NN * HH / 4);
        zero_kernel<<<(NN * HH / 4 + 255) / 256, 256>>>(accO, NN * HH / 4);
        scatter_kernel<<<EE * (HH / 4) / 256, 256>>>(relCur, sub_idx, obj_idx,
                                                     gate[2], gate[3], accS, accO);
        objmsg_kernel<<<NN * (HH / 4) / 256, 256>>>(accS, accO, cntS, cntO, objmsg);

        // fusion: C = relu(msg)@Wih + relu(cur)@Whh + bih + bhh
        kFuse<<<dim3(HH / 128, NN / 128), 256, SM128>>>(
            objmsg, nullptr, HH, HH, objCur, nullptr, HH, HH,
            wf_hi + 0 * (size_t)HH * HH, wf_lo + 0 * (size_t)HH * HH, HH,
            wf_hi + 1 * (size_t)HH * HH, wf_lo + 1 * (size_t)HH * HH, HH,
            nullptr, nullptr, nullptr, nullptr,
            bih_objf, bhh_objf, objNext, HH, 0);
        kFuse<<<dim3(HH / 128, EE / 128), 256, SM128>>>(
            relmsg, nullptr, HH, HH, relCur, nullptr, HH, HH,
            wf_hi + 2 * (size_t)HH * HH, wf_lo + 2 * (size_t)HH * HH, HH,
            wf_hi + 3 * (size_t)HH * HH, wf_lo + 3 * (size_t)HH * HH, HH,
            nullptr, nullptr, nullptr, nullptr,
            bih_relf, bhh_relf, relNext, HH, 0);

        objCur = objNext;
        relCur = relNext;
    }
}